// round 1
// baseline (speedup 1.0000x reference)
#include <cuda_runtime.h>

#define BATCH 16
#define IMG_H 1024
#define IMG_W 1024
#define WPR   32            // 32-bit words per row (1024/32)
#define NROWS (BATCH * IMG_H)
#define NTOT  ((double)BATCH * IMG_H * IMG_W)

// Scratch (allocation-free: __device__ globals)
__device__ unsigned int g_lbits[NROWS * WPR];   // label bits, 2 MB
__device__ unsigned int g_hbits[NROWS * WPR];   // horizontal-OR (radius 7) bits, 2 MB
__device__ double g_sum[3];                     // sums of -log q for E, B, T
__device__ int    g_cnt[3];                     // counts for E, B, T

// ---------------------------------------------------------------------------
// Kernel A: one block per row (1024 threads). Bit-pack label via ballot,
// then horizontal OR over radius 7 with 64-bit shift doubling.
// Block 0 also zeroes the global accumulators (runs before main_kernel).
// ---------------------------------------------------------------------------
__global__ void pack_hor(const int* __restrict__ label) {
    __shared__ unsigned int srow[WPR];
    const int row = blockIdx.x;        // 0 .. NROWS-1  (batch*1024 + y)
    const int t   = threadIdx.x;       // 0 .. 1023

    if (blockIdx.x == 0 && t < 3) { g_sum[t] = 0.0; g_cnt[t] = 0; }

    const int v = label[row * IMG_W + t];
    const unsigned int b = __ballot_sync(0xffffffffu, v != 0);
    const int lane = t & 31;
    const int w    = t >> 5;
    if (lane == 0) {
        srow[w] = b;
        g_lbits[row * WPR + w] = b;
    }
    __syncthreads();

    if (t < WPR) {
        const unsigned int wl = (t > 0)       ? srow[t - 1] : 0u;
        const unsigned int wc = srow[t];
        const unsigned int wr = (t < WPR - 1) ? srow[t + 1] : 0u;
        // OR of pixels x..x+7 : low word = wc, high = wr, fold right-shifts 0..7
        unsigned long long a = (unsigned long long)wc | ((unsigned long long)wr << 32);
        a |= a >> 1; a |= a >> 2; a |= a >> 4;
        // OR of pixels x-7..x : low word = wl, high = wc, fold left-shifts 0..7
        unsigned long long c = (unsigned long long)wl | ((unsigned long long)wc << 32);
        c |= c << 1; c |= c << 2; c |= c << 4;
        g_hbits[row * WPR + t] = (unsigned int)a | (unsigned int)(c >> 32);
    }
}

// ---------------------------------------------------------------------------
// Kernel B: one warp per image row. lane = word index within the row.
// Vertical OR over 15 rows of hbits (L2-resident) -> edge word.
// Pred read fully coalesced as float4; per-pixel word/bit fetched via shfl.
// ---------------------------------------------------------------------------
__global__ void __launch_bounds__(256) main_kernel(const float* __restrict__ Pred) {
    const int lane  = threadIdx.x & 31;
    const int wid   = threadIdx.x >> 5;                  // 0..7 (8 warps/block)
    const int row   = blockIdx.x * 8 + wid;              // global row 0..NROWS-1
    const int y     = row & (IMG_H - 1);                 // row within image

    // Vertical OR (zero padding outside the image)
    const unsigned int* hrow = g_hbits + (size_t)row * WPR;
    unsigned int ew = 0;
#pragma unroll
    for (int dy = -7; dy <= 7; dy++) {
        const int yy = y + dy;
        if (yy >= 0 && yy < IMG_H) ew |= hrow[dy * WPR + lane];
    }
    const unsigned int lw = g_lbits[(size_t)row * WPR + lane];

    // Exact counts: E = label, B = edge & ~label, T = ~edge (edge >= label)
    int cE = __popc(lw);
    int cB = __popc(ew & ~lw);
    int cT = 32 - __popc(ew);

    float sE = 0.f, sB = 0.f, sT = 0.f;
    const float4* prow = (const float4*)(Pred + (size_t)row * IMG_W);

#pragma unroll
    for (int k = 0; k < 8; k++) {
        // lane handles pixels 128k + 4*lane .. +3  -> contiguous 512B per warp
        const float4 p4 = prow[k * 32 + lane];
        const int widx  = 4 * k + (lane >> 3);           // word containing these 4 px
        const unsigned int lwk = __shfl_sync(0xffffffffu, lw, widx);
        const unsigned int ewk = __shfl_sync(0xffffffffu, ew, widx);
        const int bit0  = (lane & 7) * 4;
        const float p[4] = { p4.x, p4.y, p4.z, p4.w };
#pragma unroll
        for (int j = 0; j < 4; j++) {
            const int tl = (lwk >> (bit0 + j)) & 1;
            const int el = (ewk >> (bit0 + j)) & 1;
            const float q  = tl ? p[j] : (1.0f - p[j]);
            const float nl = -__logf(q);                  // bce for this pixel
            if (tl)      sE += nl;
            else if (el) sB += nl;
            else         sT += nl;
        }
    }

    // Warp reduction
#pragma unroll
    for (int off = 16; off; off >>= 1) {
        sE += __shfl_xor_sync(0xffffffffu, sE, off);
        sB += __shfl_xor_sync(0xffffffffu, sB, off);
        sT += __shfl_xor_sync(0xffffffffu, sT, off);
    }
    cE = __reduce_add_sync(0xffffffffu, cE);
    cB = __reduce_add_sync(0xffffffffu, cB);
    cT = __reduce_add_sync(0xffffffffu, cT);

    // Block reduction (8 warps) -> one set of atomics per block
    __shared__ float  fs[3][8];
    __shared__ int    is[3][8];
    if (lane == 0) {
        fs[0][wid] = sE; fs[1][wid] = sB; fs[2][wid] = sT;
        is[0][wid] = cE; is[1][wid] = cB; is[2][wid] = cT;
    }
    __syncthreads();
    if (threadIdx.x == 0) {
        double bE = 0, bB = 0, bT = 0;
        int    iE = 0, iB = 0, iT = 0;
#pragma unroll
        for (int i = 0; i < 8; i++) {
            bE += fs[0][i]; bB += fs[1][i]; bT += fs[2][i];
            iE += is[0][i]; iB += is[1][i]; iT += is[2][i];
        }
        atomicAdd(&g_sum[0], bE);
        atomicAdd(&g_sum[1], bB);
        atomicAdd(&g_sum[2], bT);
        atomicAdd(&g_cnt[0], iE);
        atomicAdd(&g_cnt[1], iB);
        atomicAdd(&g_cnt[2], iT);
    }
}

// ---------------------------------------------------------------------------
// Kernel C: combine into the scalar loss.
// ---------------------------------------------------------------------------
__global__ void finalize(float* __restrict__ out) {
    const double N  = NTOT;
    const double wE = (1.0 - (double)g_cnt[0] / N) * 1.0;
    const double wB = (1.0 - (double)g_cnt[1] / N) * 0.8;
    const double wT = (1.0 - (double)g_cnt[2] / N) * 0.5;
    out[0] = (float)((wE * g_sum[0] + wB * g_sum[1] + wT * g_sum[2]) / N);
}

extern "C" void kernel_launch(void* const* d_in, const int* in_sizes, int n_in,
                              void* d_out, int out_size) {
    const float* Pred  = (const float*)d_in[0];
    const int*   label = (const int*)d_in[1];
    (void)in_sizes; (void)n_in; (void)out_size;

    pack_hor<<<NROWS, 1024>>>(label);
    main_kernel<<<NROWS / 8, 256>>>(Pred);
    finalize<<<1, 1>>>((float*)d_out);
}

// round 2
// speedup vs baseline: 1.8356x; 1.8356x over previous
#include <cuda_runtime.h>

#define BATCH 16
#define IMG_H 1024
#define IMG_W 1024
#define WPR   32                 // 32-bit words per row (1024/32)
#define NROWS (BATCH * IMG_H)
#define NTOT  ((double)BATCH * IMG_H * IMG_W)
#define ROWS_PER_BLK 8           // pack kernel: rows per 256-thread block

// Scratch (allocation-free: __device__ globals)
__device__ unsigned int g_lbits[NROWS * WPR];   // label bits, 2 MB
__device__ unsigned int g_hbits[NROWS * WPR];   // horizontal-OR (r=7) bits, 2 MB
__device__ double g_sum[3];                     // sums of lg2(q): All, Edge, Lab
__device__ int    g_cnt[2];                     // counts: Lab, Edge
__device__ int    g_done;                       // arrival counter (reset each run)

// ---------------------------------------------------------------------------
// Kernel A: 256 threads handle 8 rows (2048 int4 = 8192 px). Each thread does
// 8 coalesced int4 loads (128 B, MLP=8), builds a 4-bit nibble, shuffle-folds
// groups of 8 lanes into one 32-bit word. Then 256 threads do the horizontal
// radius-7 OR (one word each) via 64-bit shift doubling.
// ---------------------------------------------------------------------------
__global__ void __launch_bounds__(256) pack_hor(const int* __restrict__ label) {
    __shared__ unsigned int sw[ROWS_PER_BLK * WPR];    // 256 packed words
    const int t    = threadIdx.x;
    const int lane = t & 31;

    if (blockIdx.x == 0 && t < 3) {
        g_sum[t] = 0.0;
        if (t < 2) g_cnt[t] = 0;
    }

    const int4* lab4 = (const int4*)label + (size_t)blockIdx.x * (ROWS_PER_BLK * WPR * 8);

#pragma unroll
    for (int k = 0; k < 8; k++) {
        const int i = k * 256 + t;                      // int4 index within block
        const int4 v = lab4[i];
        unsigned int nib = (v.x != 0 ? 1u : 0u) | (v.y != 0 ? 2u : 0u)
                         | (v.z != 0 ? 4u : 0u) | (v.w != 0 ? 8u : 0u);
        unsigned int val = nib << (4 * (lane & 7));
        val |= __shfl_xor_sync(0xffffffffu, val, 1);
        val |= __shfl_xor_sync(0xffffffffu, val, 2);
        val |= __shfl_xor_sync(0xffffffffu, val, 4);
        if ((lane & 7) == 0) sw[i >> 3] = val;          // word = 8 int4 = 32 px
    }
    __syncthreads();

    // One word per thread: t = r*32 + w (r = row-in-block, w = word-in-row)
    const int w = t & 31;
    const unsigned int wl = (w > 0)       ? sw[t - 1] : 0u;
    const unsigned int wc = sw[t];
    const unsigned int wr = (w < WPR - 1) ? sw[t + 1] : 0u;
    unsigned long long a = (unsigned long long)wc | ((unsigned long long)wr << 32);
    a |= a >> 1; a |= a >> 2; a |= a >> 4;              // OR of px x..x+7
    unsigned long long c = (unsigned long long)wl | ((unsigned long long)wc << 32);
    c |= c << 1; c |= c << 2; c |= c << 4;              // OR of px x-7..x
    const size_t gidx = (size_t)blockIdx.x * (ROWS_PER_BLK * WPR) + t;
    g_lbits[gidx] = wc;
    g_hbits[gidx] = (unsigned int)a | (unsigned int)(c >> 32);
}

// ---------------------------------------------------------------------------
// Kernel B: one warp per image row (8 warps/block). Vertical OR over 15
// hbits rows (L2-resident), then per-pixel lg2(q) with 3 accumulators:
// sAll (always), sEdge (@edge), sLab (@label). Last block finalizes.
// ---------------------------------------------------------------------------
__global__ void __launch_bounds__(256) main_kernel(const float* __restrict__ Pred,
                                                   float* __restrict__ out) {
    const int lane = threadIdx.x & 31;
    const int wid  = threadIdx.x >> 5;
    const int row  = blockIdx.x * 8 + wid;
    const int y    = row & (IMG_H - 1);

    // Vertical OR (zero outside image)
    const unsigned int* hrow = g_hbits + (size_t)row * WPR;
    unsigned int ew = 0;
#pragma unroll
    for (int dy = -7; dy <= 7; dy++) {
        const int yy = y + dy;
        if (yy >= 0 && yy < IMG_H) ew |= hrow[dy * WPR + lane];
    }
    const unsigned int lw = g_lbits[(size_t)row * WPR + lane];

    int cLab  = __popc(lw);
    int cEdge = __popc(ew);

    float sAll = 0.f, sEdge = 0.f, sLab = 0.f;
    const float4* prow = (const float4*)(Pred + (size_t)row * IMG_W);

#pragma unroll
    for (int k = 0; k < 8; k++) {
        const float4 p4 = prow[k * 32 + lane];          // contiguous 512B/warp
        const int widx  = 4 * k + (lane >> 3);
        const unsigned int lwk = __shfl_sync(0xffffffffu, lw, widx) >> (4 * (lane & 7));
        const unsigned int ewk = __shfl_sync(0xffffffffu, ew, widx) >> (4 * (lane & 7));
        const float p[4] = { p4.x, p4.y, p4.z, p4.w };
#pragma unroll
        for (int j = 0; j < 4; j++) {
            const bool tl = (lwk >> j) & 1;
            const bool el = (ewk >> j) & 1;
            const float q  = tl ? p[j] : (1.0f - p[j]);
            const float l2 = __log2f(q);                // -ln scale folded at end
            sAll += l2;
            if (el) sEdge += l2;
            if (tl) sLab  += l2;
        }
    }

#pragma unroll
    for (int off = 16; off; off >>= 1) {
        sAll  += __shfl_xor_sync(0xffffffffu, sAll,  off);
        sEdge += __shfl_xor_sync(0xffffffffu, sEdge, off);
        sLab  += __shfl_xor_sync(0xffffffffu, sLab,  off);
    }
    cLab  = __reduce_add_sync(0xffffffffu, cLab);
    cEdge = __reduce_add_sync(0xffffffffu, cEdge);

    __shared__ float fs[3][8];
    __shared__ int   is[2][8];
    if (lane == 0) {
        fs[0][wid] = sAll; fs[1][wid] = sEdge; fs[2][wid] = sLab;
        is[0][wid] = cLab; is[1][wid] = cEdge;
    }
    __syncthreads();
    if (threadIdx.x == 0) {
        double bA = 0, bE = 0, bL = 0; int iL = 0, iE = 0;
#pragma unroll
        for (int i = 0; i < 8; i++) {
            bA += fs[0][i]; bE += fs[1][i]; bL += fs[2][i];
            iL += is[0][i]; iE += is[1][i];
        }
        atomicAdd(&g_sum[0], bA);
        atomicAdd(&g_sum[1], bE);
        atomicAdd(&g_sum[2], bL);
        atomicAdd(&g_cnt[0], iL);
        atomicAdd(&g_cnt[1], iE);
        __threadfence();
        if (atomicAdd(&g_done, 1) == (int)gridDim.x - 1) {
            g_done = 0;                                  // replay-deterministic
            const double N  = NTOT;
            const double nL = (double)g_cnt[0];          // label (E) count
            const double nE = (double)g_cnt[1];          // edge count
            const double sA = g_sum[0], sE2 = g_sum[1], sL = g_sum[2];
            const double wE = (1.0 - nL / N) * 1.0;
            const double wB = (1.0 - (nE - nL) / N) * 0.8;
            const double wT = (1.0 - (N - nE) / N) * 0.5;
            // category sums of lg2 q:  E = sL,  B = sE2 - sL,  T = sA - sE2
            const double LN2 = 0.6931471805599453;
            out[0] = (float)(-LN2 * (wE * sL + wB * (sE2 - sL) + wT * (sA - sE2)) / N);
        }
    }
}

extern "C" void kernel_launch(void* const* d_in, const int* in_sizes, int n_in,
                              void* d_out, int out_size) {
    const float* Pred  = (const float*)d_in[0];
    const int*   label = (const int*)d_in[1];
    (void)in_sizes; (void)n_in; (void)out_size;

    pack_hor<<<NROWS / ROWS_PER_BLK, 256>>>(label);
    main_kernel<<<NROWS / 8, 256>>>(Pred, (float*)d_out);
}

// round 3
// speedup vs baseline: 1.9420x; 1.0580x over previous
#include <cuda_runtime.h>

#define BATCH 16
#define IMG_H 1024
#define IMG_W 1024
#define WPR   32                 // 32-bit words per row (1024/32)
#define NROWS (BATCH * IMG_H)
#define NTOT  ((double)BATCH * IMG_H * IMG_W)
#define ROWS_PER_BLK 8

// Scratch (allocation-free: __device__ globals)
__device__ unsigned int g_lbits[NROWS * WPR];   // label bits, 2 MB
__device__ unsigned int g_hbits[NROWS * WPR];   // horizontal-OR (r=7) bits, 2 MB
__device__ double g_sum[3];                     // sums of lg2(q): All, Edge, Lab
__device__ int    g_cnt[2];                     // counts: Lab, Edge
__device__ int    g_done;                       // arrival counter (reset each run)

// ---------------------------------------------------------------------------
// Kernel A: 256 threads / 8 rows. All 8 int4 loads batched up front (MLP=8),
// labels are 0/1 so nibble = v.x | v.y<<1 | v.z<<2 | v.w<<3. Shuffle-fold to
// 32-bit words, then horizontal radius-7 OR via 64-bit shift doubling.
// ---------------------------------------------------------------------------
__global__ void __launch_bounds__(256) pack_hor(const int* __restrict__ label) {
    __shared__ unsigned int sw[ROWS_PER_BLK * WPR];
    const int t    = threadIdx.x;
    const int lane = t & 31;

    const int4* lab4 = (const int4*)label + (size_t)blockIdx.x * (ROWS_PER_BLK * WPR * 8);
    int4 v[8];
#pragma unroll
    for (int k = 0; k < 8; k++) v[k] = lab4[k * 256 + t];

    if (blockIdx.x == 0 && t < 3) {
        g_sum[t] = 0.0;
        if (t < 2) g_cnt[t] = 0;
    }

#pragma unroll
    for (int k = 0; k < 8; k++) {
        unsigned int nib = (unsigned)v[k].x | ((unsigned)v[k].y << 1)
                         | ((unsigned)v[k].z << 2) | ((unsigned)v[k].w << 3);
        unsigned int val = nib << (4 * (lane & 7));
        val |= __shfl_xor_sync(0xffffffffu, val, 1);
        val |= __shfl_xor_sync(0xffffffffu, val, 2);
        val |= __shfl_xor_sync(0xffffffffu, val, 4);
        if ((lane & 7) == 0) sw[(k * 256 + t) >> 3] = val;
    }
    __syncthreads();

    const int w = t & 31;
    const unsigned int wl = (w > 0)       ? sw[t - 1] : 0u;
    const unsigned int wc = sw[t];
    const unsigned int wr = (w < WPR - 1) ? sw[t + 1] : 0u;
    unsigned long long a = (unsigned long long)wc | ((unsigned long long)wr << 32);
    a |= a >> 1; a |= a >> 2; a |= a >> 4;              // OR of px x..x+7
    unsigned long long c = (unsigned long long)wl | ((unsigned long long)wc << 32);
    c |= c << 1; c |= c << 2; c |= c << 4;              // OR of px x-7..x
    const size_t gidx = (size_t)blockIdx.x * (ROWS_PER_BLK * WPR) + t;
    g_lbits[gidx] = wc;
    g_hbits[gidx] = (unsigned int)a | (unsigned int)(c >> 32);
}

// ---------------------------------------------------------------------------
// Kernel B: 8 warps / 8 rows per block. Pred loads batched first (MLP=8).
// Vertical OR done cooperatively via smem (22 hbits rows per block, loaded
// once). Lane's 32 mask bits pre-transposed into mylw/myew so the compute
// loop is pure immediate-shift bit tests. Last block finalizes the scalar.
// ---------------------------------------------------------------------------
__global__ void __launch_bounds__(256) main_kernel(const float* __restrict__ Pred,
                                                   float* __restrict__ out) {
    __shared__ unsigned int se[22 * WPR];               // hbits rows y0-7 .. y0+14
    const int t    = threadIdx.x;
    const int lane = t & 31;
    const int wid  = t >> 5;
    const int row0 = blockIdx.x * 8;                    // global row of warp 0
    const int y0   = row0 & (IMG_H - 1);
    const int imgbase = row0 - y0;                      // global row of image top
    const int row  = row0 + wid;

    // 1) Pred: 8 front-batched coalesced LDG.128 (512B/warp each)
    const float4* prow = (const float4*)(Pred + (size_t)row * IMG_W);
    float4 p[8];
#pragma unroll
    for (int k = 0; k < 8; k++) p[k] = prow[k * 32 + lane];

    // 2) Cooperative smem fill: 22 clipped hbits rows (704 words)
    for (int i = t; i < 22 * WPR; i += 256) {
        const int yy = y0 - 7 + (i >> 5);
        unsigned int v = 0;
        if (yy >= 0 && yy < IMG_H)
            v = g_hbits[(size_t)(imgbase + yy) * WPR + (i & 31)];
        se[i] = v;
    }
    const unsigned int lw = g_lbits[(size_t)row * WPR + lane];
    __syncthreads();

    // 3) Vertical OR from smem: warp wid's y = y0+wid -> smem rows wid..wid+14
    unsigned int ew = 0;
#pragma unroll
    for (int dy = 0; dy < 15; dy++) ew |= se[(wid + dy) * WPR + lane];

    int cLab  = __popc(lw);
    int cEdge = __popc(ew);

    // 4) Transpose: lane's pixel i (=4k+j) lives in word 4k+(lane>>3),
    //    nibble offset 4*(lane&7). Pack into mylw/myew, bit i = pixel i.
    unsigned int mylw = 0, myew = 0;
    const int nsh = 4 * (lane & 7);
#pragma unroll
    for (int k = 0; k < 8; k++) {
        const int widx = 4 * k + (lane >> 3);
        mylw |= ((__shfl_sync(0xffffffffu, lw, widx) >> nsh) & 0xFu) << (4 * k);
        myew |= ((__shfl_sync(0xffffffffu, ew, widx) >> nsh) & 0xFu) << (4 * k);
    }

    // 5) Pure-ALU compute loop, fully unrolled, immediate bit tests
    float sAll = 0.f, sEdge = 0.f, sLab = 0.f;
    const float* pf = (const float*)p;                  // pixel i = pf[i]
#pragma unroll
    for (int i = 0; i < 32; i++) {
        const bool tl = (mylw >> i) & 1u;
        const bool el = (myew >> i) & 1u;
        const float pv = pf[i];
        const float q  = tl ? pv : 1.0f - pv;
        const float l2 = __log2f(q);
        sAll += l2;
        if (el) sEdge += l2;
        if (tl) sLab  += l2;
    }

#pragma unroll
    for (int off = 16; off; off >>= 1) {
        sAll  += __shfl_xor_sync(0xffffffffu, sAll,  off);
        sEdge += __shfl_xor_sync(0xffffffffu, sEdge, off);
        sLab  += __shfl_xor_sync(0xffffffffu, sLab,  off);
    }
    cLab  = __reduce_add_sync(0xffffffffu, cLab);
    cEdge = __reduce_add_sync(0xffffffffu, cEdge);

    __shared__ float fs[3][8];
    __shared__ int   is[2][8];
    if (lane == 0) {
        fs[0][wid] = sAll; fs[1][wid] = sEdge; fs[2][wid] = sLab;
        is[0][wid] = cLab; is[1][wid] = cEdge;
    }
    __syncthreads();
    if (t == 0) {
        double bA = 0, bE = 0, bL = 0; int iL = 0, iE = 0;
#pragma unroll
        for (int i = 0; i < 8; i++) {
            bA += fs[0][i]; bE += fs[1][i]; bL += fs[2][i];
            iL += is[0][i]; iE += is[1][i];
        }
        atomicAdd(&g_sum[0], bA);
        atomicAdd(&g_sum[1], bE);
        atomicAdd(&g_sum[2], bL);
        atomicAdd(&g_cnt[0], iL);
        atomicAdd(&g_cnt[1], iE);
        __threadfence();
        if (atomicAdd(&g_done, 1) == (int)gridDim.x - 1) {
            g_done = 0;                                  // replay-deterministic
            const double N  = NTOT;
            const double nL = (double)g_cnt[0];          // label (E) count
            const double nE = (double)g_cnt[1];          // edge count
            const double sA = g_sum[0], sE2 = g_sum[1], sL = g_sum[2];
            const double wE = (1.0 - nL / N) * 1.0;
            const double wB = (1.0 - (nE - nL) / N) * 0.8;
            const double wT = (1.0 - (N - nE) / N) * 0.5;
            const double LN2 = 0.6931471805599453;
            out[0] = (float)(-LN2 * (wE * sL + wB * (sE2 - sL) + wT * (sA - sE2)) / N);
        }
    }
}

extern "C" void kernel_launch(void* const* d_in, const int* in_sizes, int n_in,
                              void* d_out, int out_size) {
    const float* Pred  = (const float*)d_in[0];
    const int*   label = (const int*)d_in[1];
    (void)in_sizes; (void)n_in; (void)out_size;

    pack_hor<<<NROWS / ROWS_PER_BLK, 256>>>(label);
    main_kernel<<<NROWS / 8, 256>>>(Pred, (float*)d_out);
}

// round 4
// speedup vs baseline: 2.0114x; 1.0357x over previous
#include <cuda_runtime.h>

#define BATCH 16
#define IMG_H 1024
#define IMG_W 1024
#define WPR   32                 // 32-bit words per row (1024/32)
#define NROWS (BATCH * IMG_H)
#define NTOT  ((double)BATCH * IMG_H * IMG_W)
#define ROWS_PER_BLK 8

// Scratch (allocation-free: __device__ globals)
__device__ unsigned int g_lbits[NROWS * WPR];   // label bits, 2 MB
__device__ unsigned int g_hbits[NROWS * WPR];   // horizontal-OR (r=7) bits, 2 MB
__device__ double g_sum[3];                     // sums of lg2(q): All, Edge, Lab
__device__ int    g_cnt[2];                     // counts: Lab, Edge
__device__ int    g_done;                       // arrival counter (reset each run)

// ---------------------------------------------------------------------------
// Kernel A: 256 threads / 8 rows. All 8 int4 loads batched up front (MLP=8),
// labels are 0/1 so nibble = v.x | v.y<<1 | v.z<<2 | v.w<<3. Shuffle-fold to
// 32-bit words, then horizontal radius-7 OR via 64-bit shift doubling.
// ---------------------------------------------------------------------------
__global__ void __launch_bounds__(256) pack_hor(const int* __restrict__ label) {
    __shared__ unsigned int sw[ROWS_PER_BLK * WPR];
    const int t    = threadIdx.x;
    const int lane = t & 31;

    const int4* lab4 = (const int4*)label + (size_t)blockIdx.x * (ROWS_PER_BLK * WPR * 8);
    int4 v[8];
#pragma unroll
    for (int k = 0; k < 8; k++) v[k] = lab4[k * 256 + t];

    if (blockIdx.x == 0 && t < 3) {
        g_sum[t] = 0.0;
        if (t < 2) g_cnt[t] = 0;
    }

#pragma unroll
    for (int k = 0; k < 8; k++) {
        unsigned int nib = (unsigned)v[k].x | ((unsigned)v[k].y << 1)
                         | ((unsigned)v[k].z << 2) | ((unsigned)v[k].w << 3);
        unsigned int val = nib << (4 * (lane & 7));
        val |= __shfl_xor_sync(0xffffffffu, val, 1);
        val |= __shfl_xor_sync(0xffffffffu, val, 2);
        val |= __shfl_xor_sync(0xffffffffu, val, 4);
        if ((lane & 7) == 0) sw[(k * 256 + t) >> 3] = val;
    }
    __syncthreads();

    const int w = t & 31;
    const unsigned int wl = (w > 0)       ? sw[t - 1] : 0u;
    const unsigned int wc = sw[t];
    const unsigned int wr = (w < WPR - 1) ? sw[t + 1] : 0u;
    unsigned long long a = (unsigned long long)wc | ((unsigned long long)wr << 32);
    a |= a >> 1; a |= a >> 2; a |= a >> 4;              // OR of px x..x+7
    unsigned long long c = (unsigned long long)wl | ((unsigned long long)wc << 32);
    c |= c << 1; c |= c << 2; c |= c << 4;              // OR of px x-7..x
    const size_t gidx = (size_t)blockIdx.x * (ROWS_PER_BLK * WPR) + t;
    g_lbits[gidx] = wc;
    g_hbits[gidx] = (unsigned int)a | (unsigned int)(c >> 32);
}

// ---------------------------------------------------------------------------
// Kernel B: 8 warps / 8 rows per block. Pred loads batched first (MLP=8) and
// KEPT IN REGISTERS (component access only — no pointer cast). Vertical OR
// via smem; per-lane mask bits pre-transposed into mylw/myew. Split
// accumulators for ILP. Last block finalizes the scalar.
// ---------------------------------------------------------------------------
__global__ void __launch_bounds__(256) main_kernel(const float* __restrict__ Pred,
                                                   float* __restrict__ out) {
    __shared__ unsigned int se[22 * WPR];               // hbits rows y0-7 .. y0+14
    const int t    = threadIdx.x;
    const int lane = t & 31;
    const int wid  = t >> 5;
    const int row0 = blockIdx.x * 8;
    const int y0   = row0 & (IMG_H - 1);
    const int imgbase = row0 - y0;
    const int row  = row0 + wid;

    // 1) Pred: 8 front-batched coalesced LDG.128 (512B/warp each), reg-resident
    const float4* prow = (const float4*)(Pred + (size_t)row * IMG_W);
    float4 p[8];
#pragma unroll
    for (int k = 0; k < 8; k++) p[k] = prow[k * 32 + lane];

    // 2) Cooperative smem fill: 22 clipped hbits rows (704 words)
    for (int i = t; i < 22 * WPR; i += 256) {
        const int yy = y0 - 7 + (i >> 5);
        unsigned int v = 0;
        if (yy >= 0 && yy < IMG_H)
            v = g_hbits[(size_t)(imgbase + yy) * WPR + (i & 31)];
        se[i] = v;
    }
    const unsigned int lw = g_lbits[(size_t)row * WPR + lane];
    __syncthreads();

    // 3) Vertical OR from smem
    unsigned int ew = 0;
#pragma unroll
    for (int dy = 0; dy < 15; dy++) ew |= se[(wid + dy) * WPR + lane];

    int cLab  = __popc(lw);
    int cEdge = __popc(ew);

    // 4) Transpose: lane's pixel i (=4k+j) is word 4k+(lane>>3), nib 4*(lane&7)
    unsigned int mylw = 0, myew = 0;
    const int nsh = 4 * (lane & 7);
#pragma unroll
    for (int k = 0; k < 8; k++) {
        const int widx = 4 * k + (lane >> 3);
        mylw |= ((__shfl_sync(0xffffffffu, lw, widx) >> nsh) & 0xFu) << (4 * k);
        myew |= ((__shfl_sync(0xffffffffu, ew, widx) >> nsh) & 0xFu) << (4 * k);
    }

    // 5) Compute: component access only (no spill), split accumulators
    float sAll0 = 0.f, sEdge0 = 0.f, sLab0 = 0.f;
    float sAll1 = 0.f, sEdge1 = 0.f, sLab1 = 0.f;

#define PIX(pv, bit, sA, sE, sL)                                   \
    {                                                              \
        const bool tl = (mylw >> (bit)) & 1u;                      \
        const bool el = (myew >> (bit)) & 1u;                      \
        const float q  = tl ? (pv) : 1.0f - (pv);                  \
        const float l2 = __log2f(q);                               \
        sA += l2;                                                  \
        if (el) sE += l2;                                          \
        if (tl) sL += l2;                                          \
    }

#pragma unroll
    for (int k = 0; k < 8; k += 2) {
        PIX(p[k].x,     4 * k + 0, sAll0, sEdge0, sLab0)
        PIX(p[k].y,     4 * k + 1, sAll0, sEdge0, sLab0)
        PIX(p[k].z,     4 * k + 2, sAll0, sEdge0, sLab0)
        PIX(p[k].w,     4 * k + 3, sAll0, sEdge0, sLab0)
        PIX(p[k + 1].x, 4 * k + 4, sAll1, sEdge1, sLab1)
        PIX(p[k + 1].y, 4 * k + 5, sAll1, sEdge1, sLab1)
        PIX(p[k + 1].z, 4 * k + 6, sAll1, sEdge1, sLab1)
        PIX(p[k + 1].w, 4 * k + 7, sAll1, sEdge1, sLab1)
    }
#undef PIX

    float sAll = sAll0 + sAll1, sEdge = sEdge0 + sEdge1, sLab = sLab0 + sLab1;

#pragma unroll
    for (int off = 16; off; off >>= 1) {
        sAll  += __shfl_xor_sync(0xffffffffu, sAll,  off);
        sEdge += __shfl_xor_sync(0xffffffffu, sEdge, off);
        sLab  += __shfl_xor_sync(0xffffffffu, sLab,  off);
    }
    cLab  = __reduce_add_sync(0xffffffffu, cLab);
    cEdge = __reduce_add_sync(0xffffffffu, cEdge);

    __shared__ float fs[3][8];
    __shared__ int   is[2][8];
    if (lane == 0) {
        fs[0][wid] = sAll; fs[1][wid] = sEdge; fs[2][wid] = sLab;
        is[0][wid] = cLab; is[1][wid] = cEdge;
    }
    __syncthreads();
    if (t == 0) {
        double bA = 0, bE = 0, bL = 0; int iL = 0, iE = 0;
#pragma unroll
        for (int i = 0; i < 8; i++) {
            bA += fs[0][i]; bE += fs[1][i]; bL += fs[2][i];
            iL += is[0][i]; iE += is[1][i];
        }
        atomicAdd(&g_sum[0], bA);
        atomicAdd(&g_sum[1], bE);
        atomicAdd(&g_sum[2], bL);
        atomicAdd(&g_cnt[0], iL);
        atomicAdd(&g_cnt[1], iE);
        __threadfence();
        if (atomicAdd(&g_done, 1) == (int)gridDim.x - 1) {
            g_done = 0;                                  // replay-deterministic
            const double N  = NTOT;
            const double nL = (double)g_cnt[0];          // label (E) count
            const double nE = (double)g_cnt[1];          // edge count
            const double sA = g_sum[0], sE2 = g_sum[1], sL = g_sum[2];
            const double wE = (1.0 - nL / N) * 1.0;
            const double wB = (1.0 - (nE - nL) / N) * 0.8;
            const double wT = (1.0 - (N - nE) / N) * 0.5;
            const double LN2 = 0.6931471805599453;
            out[0] = (float)(-LN2 * (wE * sL + wB * (sE2 - sL) + wT * (sA - sE2)) / N);
        }
    }
}

extern "C" void kernel_launch(void* const* d_in, const int* in_sizes, int n_in,
                              void* d_out, int out_size) {
    const float* Pred  = (const float*)d_in[0];
    const int*   label = (const int*)d_in[1];
    (void)in_sizes; (void)n_in; (void)out_size;

    pack_hor<<<NROWS / ROWS_PER_BLK, 256>>>(label);
    main_kernel<<<NROWS / 8, 256>>>(Pred, (float*)d_out);
}